// round 5
// baseline (speedup 1.0000x reference)
#include <cuda_runtime.h>
#include <cuda_bf16.h>

#define D 64
#define N_MAX 131072
#define E_MAX 2097152

// -------- device scratch --------
__device__ float g_H[N_MAX * D];
__device__ float g_A[N_MAX * D];
__device__ int   g_cnt[N_MAX];
__device__ float g_dinv[N_MAX];
__device__ int   g_rowptr[N_MAX + 1];
__device__ int   g_cursor[N_MAX];
__device__ int   g_col[E_MAX];
__device__ float g_norm[E_MAX];
__device__ int   g_elw;   // 1 = int32 edge index, 2 = int64

// -------- packed f32x2 helpers --------
__device__ __forceinline__ unsigned long long pack2(float a) {
    unsigned long long r;
    asm("mov.b64 %0, {%1, %1};" : "=l"(r) : "f"(a));
    return r;
}
__device__ __forceinline__ void ffma2(unsigned long long& d,
                                      unsigned long long a, unsigned long long b) {
    asm("fma.rn.f32x2 %0, %1, %2, %0;" : "+l"(d) : "l"(a), "l"(b));
}
__device__ __forceinline__ void unpack2(unsigned long long v, float& lo, float& hi) {
    asm("mov.b64 {%0, %1}, %2;" : "=f"(lo), "=f"(hi) : "l"(v));
}

// -------- init + dtype probe (fused) --------
__global__ void k_init(const int* __restrict__ p, int n) {
    int i = blockIdx.x * blockDim.x + threadIdx.x;
    if (i < n) { g_cnt[i] = 0; g_cursor[i] = 0; }
    if (blockIdx.x == 0 && threadIdx.x == 0) {
        int nz = 0;
#pragma unroll
        for (int k = 0; k < 64; k++) nz |= p[2 * k + 1];
        g_elw = (nz == 0) ? 2 : 1;
    }
}

// -------- degree count: 4 edges per thread, vectorized --------
__global__ void k_count(const int* __restrict__ p, int e, int n) {
    int base = (blockIdx.x * blockDim.x + threadIdx.x) * 4;
    if (base >= e) return;
    int elw = g_elw;
    int d[4];
    bool full = (base + 3 < e) && ((e & 3) == 0);
    if (elw == 1) {
        if (full) {
            int4 v = *(const int4*)(p + e + base);
            d[0] = v.x; d[1] = v.y; d[2] = v.z; d[3] = v.w;
        } else {
            for (int i = 0; i < 4; i++) d[i] = (base + i < e) ? p[e + base + i] : -1;
        }
    } else {
        const long long* q = (const long long*)p;
        if (full) {
            longlong2 v0 = *(const longlong2*)(q + e + base);
            longlong2 v1 = *(const longlong2*)(q + e + base + 2);
            d[0] = (int)v0.x; d[1] = (int)v0.y; d[2] = (int)v1.x; d[3] = (int)v1.y;
        } else {
            for (int i = 0; i < 4; i++) d[i] = (base + i < e) ? (int)q[e + base + i] : -1;
        }
    }
#pragma unroll
    for (int i = 0; i < 4; i++)
        if ((unsigned)d[i] < (unsigned)n) atomicAdd(&g_cnt[d[i]], 1);
}

// -------- single-block scan: rowptr + dinv fused --------
__global__ void __launch_bounds__(1024) k_scan(int n) {
    __shared__ int sh[1024];
    int t = threadIdx.x;
    int items = (n + 1023) >> 10;
    int lo = t * items, hi = min(n, lo + items);
    int sum = 0;
    for (int i = lo; i < hi; i++) {
        int c = g_cnt[i];
        sum += c;
        g_dinv[i] = rsqrtf((float)(c + 1));
    }
    sh[t] = sum;
    __syncthreads();
#pragma unroll
    for (int off = 1; off < 1024; off <<= 1) {
        int v = (t >= off) ? sh[t - off] : 0;
        __syncthreads();
        sh[t] += v;
        __syncthreads();
    }
    int run = sh[t] - sum;  // exclusive prefix
    for (int i = lo; i < hi; i++) {
        g_rowptr[i] = run;
        run += g_cnt[i];
    }
    if (t == 1023) g_rowptr[n] = sh[1023];
}

// -------- CSR fill: 4 edges per thread --------
__global__ void k_fill(const int* __restrict__ p, int e, int n) {
    int base = (blockIdx.x * blockDim.x + threadIdx.x) * 4;
    if (base >= e) return;
    int elw = g_elw;
    int s[4], d[4];
    bool full = (base + 3 < e) && ((e & 3) == 0);
    if (elw == 1) {
        if (full) {
            int4 vs = *(const int4*)(p + base);
            int4 vd = *(const int4*)(p + e + base);
            s[0] = vs.x; s[1] = vs.y; s[2] = vs.z; s[3] = vs.w;
            d[0] = vd.x; d[1] = vd.y; d[2] = vd.z; d[3] = vd.w;
        } else {
            for (int i = 0; i < 4; i++) {
                s[i] = (base + i < e) ? p[base + i] : -1;
                d[i] = (base + i < e) ? p[e + base + i] : -1;
            }
        }
    } else {
        const long long* q = (const long long*)p;
        if (full) {
            longlong2 s0 = *(const longlong2*)(q + base);
            longlong2 s1 = *(const longlong2*)(q + base + 2);
            longlong2 d0 = *(const longlong2*)(q + e + base);
            longlong2 d1 = *(const longlong2*)(q + e + base + 2);
            s[0] = (int)s0.x; s[1] = (int)s0.y; s[2] = (int)s1.x; s[3] = (int)s1.y;
            d[0] = (int)d0.x; d[1] = (int)d0.y; d[2] = (int)d1.x; d[3] = (int)d1.y;
        } else {
            for (int i = 0; i < 4; i++) {
                s[i] = (base + i < e) ? (int)q[base + i] : -1;
                d[i] = (base + i < e) ? (int)q[e + base + i] : -1;
            }
        }
    }
#pragma unroll
    for (int i = 0; i < 4; i++) {
        if ((unsigned)s[i] < (unsigned)n && (unsigned)d[i] < (unsigned)n) {
            int pos = g_rowptr[d[i]] + atomicAdd(&g_cursor[d[i]], 1);
            g_col[pos] = s[i];
            g_norm[pos] = g_dinv[s[i]] * g_dinv[d[i]];
        }
    }
}

// -------- GEMM: g_H[n,64] = A[n,64] @ W[64,64], packed f32x2 FMA --------
// 128 threads/block, 64x64 tile, 4 rows x 8 cols per thread.
template <int SRC>
__global__ void __launch_bounds__(128) k_gemm(const float* __restrict__ Aext,
                                              const float* __restrict__ W, int n) {
    __shared__ float As[64][65];
    __shared__ float Ws[64][64];

    const float* A = (SRC == 0) ? Aext : (const float*)g_A;
    int tid = threadIdx.x;
    int rowbase = blockIdx.x * 64;

#pragma unroll
    for (int i = 0; i < 8; i++) {
        int idx = tid + i * 128;
        int r = idx >> 4;
        int f4 = idx & 15;
        float4 va = (rowbase + r < n)
            ? *(const float4*)(A + (size_t)(rowbase + r) * 64 + f4 * 4)
            : make_float4(0.f, 0.f, 0.f, 0.f);
        As[r][f4 * 4 + 0] = va.x; As[r][f4 * 4 + 1] = va.y;
        As[r][f4 * 4 + 2] = va.z; As[r][f4 * 4 + 3] = va.w;
        *(float4*)(&Ws[r][f4 * 4]) = *(const float4*)(W + r * 64 + f4 * 4);
    }
    __syncthreads();

    int tx = tid & 7;    // cols tx*8..+7
    int ty = tid >> 3;   // rows ty*4..+3

    unsigned long long acc2[4][4];
#pragma unroll
    for (int r = 0; r < 4; r++)
#pragma unroll
        for (int c = 0; c < 4; c++) acc2[r][c] = 0ull;

#pragma unroll 4
    for (int k = 0; k < 64; k++) {
        const unsigned long long* Wrow = (const unsigned long long*)(&Ws[k][tx * 8]);
        unsigned long long w0 = Wrow[0], w1 = Wrow[1], w2 = Wrow[2], w3 = Wrow[3];
#pragma unroll
        for (int r = 0; r < 4; r++) {
            unsigned long long ar = pack2(As[ty * 4 + r][k]);
            ffma2(acc2[r][0], ar, w0);
            ffma2(acc2[r][1], ar, w1);
            ffma2(acc2[r][2], ar, w2);
            ffma2(acc2[r][3], ar, w3);
        }
    }

#pragma unroll
    for (int r = 0; r < 4; r++) {
        int row = rowbase + ty * 4 + r;
        if (row < n) {
            float4 o0, o1;
            unpack2(acc2[r][0], o0.x, o0.y);
            unpack2(acc2[r][1], o0.z, o0.w);
            unpack2(acc2[r][2], o1.x, o1.y);
            unpack2(acc2[r][3], o1.z, o1.w);
            *(float4*)(g_H + (size_t)row * 64 + tx * 8)     = o0;
            *(float4*)(g_H + (size_t)row * 64 + tx * 8 + 4) = o1;
        }
    }
}

// -------- Aggregation: half-warp float4, 2 edges per iteration --------
template <int DSTOUT>
__global__ void k_agg(const float* __restrict__ bias, float* __restrict__ outext,
                      int n) {
    int gw = (blockIdx.x * blockDim.x + threadIdx.x) >> 5;
    int lane = threadIdx.x & 31;
    if (gw >= n) return;
    int i = gw;
    int l16 = lane & 15;
    int half = lane >> 4;

    const float4* H4 = (const float4*)g_H;
    float di = g_dinv[i];
    float sn = di * di;
    float4 acc;
    if (half == 0) {
        float4 h = H4[i * 16 + l16];
        acc = make_float4(h.x * sn, h.y * sn, h.z * sn, h.w * sn);
    } else {
        acc = make_float4(0.f, 0.f, 0.f, 0.f);
    }

    int s = g_rowptr[i], e = g_rowptr[i + 1];
    for (int base = s; base < e; base += 32) {
        int m = min(32, e - base);
        int c = 0; float nv = 0.f;
        if (lane < m) { c = g_col[base + lane]; nv = g_norm[base + lane]; }
        int pairs = (m + 1) >> 1;
#pragma unroll 4
        for (int j = 0; j < pairs; j++) {
            int srcl = 2 * j + half;
            int   cj = __shfl_sync(0xffffffffu, c, srcl);
            float nj = __shfl_sync(0xffffffffu, nv, srcl);
            float4 hh = __ldg(&H4[cj * 16 + l16]);
            acc.x += hh.x * nj;
            acc.y += hh.y * nj;
            acc.z += hh.z * nj;
            acc.w += hh.w * nj;
        }
    }
    acc.x += __shfl_xor_sync(0xffffffffu, acc.x, 16);
    acc.y += __shfl_xor_sync(0xffffffffu, acc.y, 16);
    acc.z += __shfl_xor_sync(0xffffffffu, acc.z, 16);
    acc.w += __shfl_xor_sync(0xffffffffu, acc.w, 16);

    if (half == 0) {
        float4 bb = ((const float4*)bias)[l16];
        acc.x = fmaxf(acc.x + bb.x, 0.f);
        acc.y = fmaxf(acc.y + bb.y, 0.f);
        acc.z = fmaxf(acc.z + bb.z, 0.f);
        acc.w = fmaxf(acc.w + bb.w, 0.f);
        float4* outp = (DSTOUT == 0) ? (float4*)g_A : (float4*)outext;
        outp[i * 16 + l16] = acc;
    }
}

// -------- launch --------
extern "C" void kernel_launch(void* const* d_in, const int* in_sizes, int n_in,
                              void* d_out, int out_size) {
    const float* x  = (const float*)d_in[0];
    const int*   ei = (const int*)d_in[1];
    const float* W0 = (const float*)d_in[2];
    const float* b0 = (const float*)d_in[3];
    const float* W1 = (const float*)d_in[4];
    const float* b1 = (const float*)d_in[5];
    const float* W2 = (const float*)d_in[6];
    const float* b2 = (const float*)d_in[7];
    float* out = (float*)d_out;

    int n = in_sizes[0] / D;
    int e = in_sizes[1] / 2;
    int e4 = (e + 3) / 4;

    k_init <<<(n + 255) / 256, 256>>>(ei, n);
    k_count<<<(e4 + 255) / 256, 256>>>(ei, e, n);
    k_scan <<<1, 1024>>>(n);
    k_fill <<<(e4 + 255) / 256, 256>>>(ei, e, n);

    int gemm_blocks = (n + 63) / 64;
    int agg_blocks  = (n + 7) / 8;

    k_gemm<0><<<gemm_blocks, 128>>>(x, W0, n);
    k_agg<0> <<<agg_blocks, 256>>>(b0, nullptr, n);
    k_gemm<1><<<gemm_blocks, 128>>>(nullptr, W1, n);
    k_agg<0> <<<agg_blocks, 256>>>(b1, nullptr, n);
    k_gemm<1><<<gemm_blocks, 128>>>(nullptr, W2, n);
    k_agg<1> <<<agg_blocks, 256>>>(b2, out, n);
}

// round 6
// speedup vs baseline: 2.2078x; 2.2078x over previous
#include <cuda_runtime.h>
#include <cuda_bf16.h>
#include <cstdint>

#define D 64
#define N_MAX 131072
#define E_MAX 2097152

// -------- device scratch --------
__device__ float g_H[N_MAX * D];
__device__ float g_A[N_MAX * D];
__device__ int   g_cnt[N_MAX];
__device__ float g_dinv[N_MAX];
__device__ int   g_rowtmp[N_MAX];
__device__ int   g_rowptr[N_MAX + 1];
__device__ int   g_cursor[N_MAX];
__device__ int   g_part[256];
__device__ int   g_col[E_MAX];
__device__ float g_norm[E_MAX];
__device__ int   g_elw;   // 1 = int32 edge index, 2 = int64

__device__ __forceinline__ uint32_t f2tf32(float f) {
    uint32_t r;
    asm("cvt.rna.tf32.f32 %0, %1;" : "=r"(r) : "f"(f));
    return r;
}

// -------- init + dtype probe --------
__global__ void k_init(const int* __restrict__ p, int n) {
    int i = blockIdx.x * blockDim.x + threadIdx.x;
    if (i < n) { g_cnt[i] = 0; g_cursor[i] = 0; }
    if (blockIdx.x == 0 && threadIdx.x == 0) {
        int nz = 0;
#pragma unroll
        for (int k = 0; k < 64; k++) nz |= p[2 * k + 1];
        g_elw = (nz == 0) ? 2 : 1;
    }
}

// -------- degree count: 4 edges/thread --------
__global__ void k_count(const int* __restrict__ p, int e, int n) {
    int base = (blockIdx.x * blockDim.x + threadIdx.x) * 4;
    if (base >= e) return;
    int elw = g_elw;
    int d[4];
    bool full = (base + 3 < e) && ((e & 3) == 0);
    if (elw == 1) {
        if (full) {
            int4 v = *(const int4*)(p + e + base);
            d[0] = v.x; d[1] = v.y; d[2] = v.z; d[3] = v.w;
        } else {
            for (int i = 0; i < 4; i++) d[i] = (base + i < e) ? p[e + base + i] : -1;
        }
    } else {
        const long long* q = (const long long*)p;
        if (full) {
            longlong2 v0 = *(const longlong2*)(q + e + base);
            longlong2 v1 = *(const longlong2*)(q + e + base + 2);
            d[0] = (int)v0.x; d[1] = (int)v0.y; d[2] = (int)v1.x; d[3] = (int)v1.y;
        } else {
            for (int i = 0; i < 4; i++) d[i] = (base + i < e) ? (int)q[e + base + i] : -1;
        }
    }
#pragma unroll
    for (int i = 0; i < 4; i++)
        if ((unsigned)d[i] < (unsigned)n) atomicAdd(&g_cnt[d[i]], 1);
}

// -------- scan A: per-1024 block scan + dinv --------
__global__ void k_scanA(int n) {
    __shared__ int sh[1024];
    int i = blockIdx.x * 1024 + threadIdx.x;
    int v = (i < n) ? g_cnt[i] : 0;
    if (i < n) g_dinv[i] = rsqrtf((float)(v + 1));
    sh[threadIdx.x] = v;
    __syncthreads();
#pragma unroll
    for (int off = 1; off < 1024; off <<= 1) {
        int t = (threadIdx.x >= off) ? sh[threadIdx.x - off] : 0;
        __syncthreads();
        sh[threadIdx.x] += t;
        __syncthreads();
    }
    if (i < n) g_rowtmp[i] = sh[threadIdx.x] - v;
    if (threadIdx.x == 1023) g_part[blockIdx.x] = sh[1023];
}

// -------- scan B: parallel scan over <=128 partials --------
__global__ void k_scanB(int nb) {
    __shared__ int sh[128];
    int t = threadIdx.x;
    int v = (t < nb) ? g_part[t] : 0;
    sh[t] = v;
    __syncthreads();
#pragma unroll
    for (int off = 1; off < 128; off <<= 1) {
        int u = (t >= off) ? sh[t - off] : 0;
        __syncthreads();
        sh[t] += u;
        __syncthreads();
    }
    if (t < nb) g_part[t] = sh[t] - v;  // exclusive
}

__global__ void k_scanC(int n, int e) {
    int i = blockIdx.x * blockDim.x + threadIdx.x;
    if (i < n) g_rowptr[i] = g_rowtmp[i] + g_part[i >> 10];
    if (i == 0) g_rowptr[n] = e;
}

// -------- CSR fill: 4 edges/thread --------
__global__ void k_fill(const int* __restrict__ p, int e, int n) {
    int base = (blockIdx.x * blockDim.x + threadIdx.x) * 4;
    if (base >= e) return;
    int elw = g_elw;
    int s[4], d[4];
    bool full = (base + 3 < e) && ((e & 3) == 0);
    if (elw == 1) {
        if (full) {
            int4 vs = *(const int4*)(p + base);
            int4 vd = *(const int4*)(p + e + base);
            s[0] = vs.x; s[1] = vs.y; s[2] = vs.z; s[3] = vs.w;
            d[0] = vd.x; d[1] = vd.y; d[2] = vd.z; d[3] = vd.w;
        } else {
            for (int i = 0; i < 4; i++) {
                s[i] = (base + i < e) ? p[base + i] : -1;
                d[i] = (base + i < e) ? p[e + base + i] : -1;
            }
        }
    } else {
        const long long* q = (const long long*)p;
        if (full) {
            longlong2 s0 = *(const longlong2*)(q + base);
            longlong2 s1 = *(const longlong2*)(q + base + 2);
            longlong2 d0 = *(const longlong2*)(q + e + base);
            longlong2 d1 = *(const longlong2*)(q + e + base + 2);
            s[0] = (int)s0.x; s[1] = (int)s0.y; s[2] = (int)s1.x; s[3] = (int)s1.y;
            d[0] = (int)d0.x; d[1] = (int)d0.y; d[2] = (int)d1.x; d[3] = (int)d1.y;
        } else {
            for (int i = 0; i < 4; i++) {
                s[i] = (base + i < e) ? (int)q[base + i] : -1;
                d[i] = (base + i < e) ? (int)q[e + base + i] : -1;
            }
        }
    }
#pragma unroll
    for (int i = 0; i < 4; i++) {
        if ((unsigned)s[i] < (unsigned)n && (unsigned)d[i] < (unsigned)n) {
            int pos = g_rowptr[d[i]] + atomicAdd(&g_cursor[d[i]], 1);
            g_col[pos] = s[i];
            g_norm[pos] = g_dinv[s[i]] * g_dinv[d[i]];
        }
    }
}

// -------- GEMM: g_H[n,64] = A[n,64] @ W[64,64] via tf32 mma.sync --------
// 128 threads (4 warps). Block tile 64 rows. Warp w: rows 16w..16w+15, all 64 cols.
// m16n8k8 tf32: per warp 8 ksteps x 8 ntiles.
template <int SRC>
__global__ void __launch_bounds__(128) k_gemm(const float* __restrict__ Aext,
                                              const float* __restrict__ W, int n) {
    __shared__ float As[64][68];   // stride 68: A-frag LDS conflict-free
    __shared__ float Ws[64][72];   // stride 72: B-frag LDS conflict-free

    const float* A = (SRC == 0) ? Aext : (const float*)g_A;
    int tid = threadIdx.x;
    int rowbase = blockIdx.x * 64;

    // stage + convert to tf32 bit pattern
#pragma unroll
    for (int i = 0; i < 8; i++) {
        int idx = tid + i * 128;      // 0..1023
        int r = idx >> 4;             // 0..63
        int f4 = idx & 15;            // 0..15
        float4 va = (rowbase + r < n)
            ? *(const float4*)(A + (size_t)(rowbase + r) * 64 + f4 * 4)
            : make_float4(0.f, 0.f, 0.f, 0.f);
        As[r][f4 * 4 + 0] = __uint_as_float(f2tf32(va.x));
        As[r][f4 * 4 + 1] = __uint_as_float(f2tf32(va.y));
        As[r][f4 * 4 + 2] = __uint_as_float(f2tf32(va.z));
        As[r][f4 * 4 + 3] = __uint_as_float(f2tf32(va.w));
        float4 vw = *(const float4*)(W + r * 64 + f4 * 4);
        Ws[r][f4 * 4 + 0] = __uint_as_float(f2tf32(vw.x));
        Ws[r][f4 * 4 + 1] = __uint_as_float(f2tf32(vw.y));
        Ws[r][f4 * 4 + 2] = __uint_as_float(f2tf32(vw.z));
        Ws[r][f4 * 4 + 3] = __uint_as_float(f2tf32(vw.w));
    }
    __syncthreads();

    int warp = tid >> 5, lane = tid & 31;
    int gid = lane >> 2;      // 0..7
    int tig = lane & 3;       // 0..3
    int ar0 = warp * 16 + gid;        // A rows for a0/a2
    int ar1 = ar0 + 8;                // A rows for a1/a3

    float acc[8][4];
#pragma unroll
    for (int t = 0; t < 8; t++)
#pragma unroll
        for (int c = 0; c < 4; c++) acc[t][c] = 0.f;

#pragma unroll
    for (int ks = 0; ks < 8; ks++) {
        int k0 = ks * 8;
        uint32_t a0 = __float_as_uint(As[ar0][k0 + tig]);
        uint32_t a1 = __float_as_uint(As[ar1][k0 + tig]);
        uint32_t a2 = __float_as_uint(As[ar0][k0 + tig + 4]);
        uint32_t a3 = __float_as_uint(As[ar1][k0 + tig + 4]);
#pragma unroll
        for (int nt = 0; nt < 8; nt++) {
            uint32_t b0 = __float_as_uint(Ws[k0 + tig][nt * 8 + gid]);
            uint32_t b1 = __float_as_uint(Ws[k0 + tig + 4][nt * 8 + gid]);
            asm volatile(
                "mma.sync.aligned.m16n8k8.row.col.f32.tf32.tf32.f32 "
                "{%0,%1,%2,%3}, {%4,%5,%6,%7}, {%8,%9}, {%0,%1,%2,%3};"
                : "+f"(acc[nt][0]), "+f"(acc[nt][1]), "+f"(acc[nt][2]), "+f"(acc[nt][3])
                : "r"(a0), "r"(a1), "r"(a2), "r"(a3), "r"(b0), "r"(b1));
        }
    }

    int row0 = rowbase + warp * 16 + gid;
    int row1 = row0 + 8;
#pragma unroll
    for (int nt = 0; nt < 8; nt++) {
        int col = nt * 8 + tig * 2;
        if (row0 < n)
            *(float2*)(g_H + (size_t)row0 * 64 + col) = make_float2(acc[nt][0], acc[nt][1]);
        if (row1 < n)
            *(float2*)(g_H + (size_t)row1 * 64 + col) = make_float2(acc[nt][2], acc[nt][3]);
    }
}

// -------- Aggregation (warp per node, float2) --------
template <int DSTOUT>
__global__ void k_agg(const float* __restrict__ bias, float* __restrict__ outext,
                      int n) {
    int gw = (blockIdx.x * blockDim.x + threadIdx.x) >> 5;
    int lane = threadIdx.x & 31;
    if (gw >= n) return;
    int i = gw;

    const float2* H2 = (const float2*)g_H;
    float di = g_dinv[i];
    float sn = di * di;
    float2 h = H2[i * 32 + lane];
    float2 acc = make_float2(h.x * sn, h.y * sn);

    int s = g_rowptr[i], e = g_rowptr[i + 1];
    for (int base = s; base < e; base += 32) {
        int m = min(32, e - base);
        int c = 0; float nv = 0.f;
        if (lane < m) { c = g_col[base + lane]; nv = g_norm[base + lane]; }
#pragma unroll 4
        for (int j = 0; j < m; j++) {
            int   cj = __shfl_sync(0xffffffffu, c, j);
            float nj = __shfl_sync(0xffffffffu, nv, j);
            float2 hh = __ldg(&H2[cj * 32 + lane]);
            acc.x += hh.x * nj;
            acc.y += hh.y * nj;
        }
    }
    float2 bb = ((const float2*)bias)[lane];
    acc.x = fmaxf(acc.x + bb.x, 0.f);
    acc.y = fmaxf(acc.y + bb.y, 0.f);
    float2* outp = (DSTOUT == 0) ? (float2*)g_A : (float2*)outext;
    outp[i * 32 + lane] = acc;
}

// -------- launch --------
extern "C" void kernel_launch(void* const* d_in, const int* in_sizes, int n_in,
                              void* d_out, int out_size) {
    const float* x  = (const float*)d_in[0];
    const int*   ei = (const int*)d_in[1];
    const float* W0 = (const float*)d_in[2];
    const float* b0 = (const float*)d_in[3];
    const float* W1 = (const float*)d_in[4];
    const float* b1 = (const float*)d_in[5];
    const float* W2 = (const float*)d_in[6];
    const float* b2 = (const float*)d_in[7];
    float* out = (float*)d_out;

    int n = in_sizes[0] / D;
    int e = in_sizes[1] / 2;
    int nb = (n + 1023) / 1024;
    int e4 = (e + 3) / 4;

    k_init <<<(n + 255) / 256, 256>>>(ei, n);
    k_count<<<(e4 + 255) / 256, 256>>>(ei, e, n);
    k_scanA<<<nb, 1024>>>(n);
    k_scanB<<<1, 128>>>(nb);
    k_scanC<<<(n + 255) / 256, 256>>>(n, e);
    k_fill <<<(e4 + 255) / 256, 256>>>(ei, e, n);

    int gemm_blocks = (n + 63) / 64;
    int agg_blocks  = (n + 7) / 8;

    k_gemm<0><<<gemm_blocks, 128>>>(x, W0, n);
    k_agg<0> <<<agg_blocks, 256>>>(b0, nullptr, n);
    k_gemm<1><<<gemm_blocks, 128>>>(nullptr, W1, n);
    k_agg<0> <<<agg_blocks, 256>>>(b1, nullptr, n);
    k_gemm<1><<<gemm_blocks, 128>>>(nullptr, W2, n);
    k_agg<1> <<<agg_blocks, 256>>>(b2, out, n);
}

// round 7
// speedup vs baseline: 2.2809x; 1.0331x over previous
#include <cuda_runtime.h>
#include <cuda_bf16.h>
#include <cstdint>

#define D 64
#define N_MAX 131072
#define E_MAX 2097152

// -------- device scratch --------
__device__ float g_H[N_MAX * D];
__device__ float g_A[N_MAX * D];
__device__ int   g_cnt[N_MAX];
__device__ float g_dinv[N_MAX];
__device__ int   g_rowtmp[N_MAX];
__device__ int   g_rowptr[N_MAX + 1];
__device__ int   g_cursor[N_MAX];
__device__ int   g_part[256];
__device__ int2  g_edge[E_MAX];   // {src col, norm bits}
__device__ int   g_elw;           // 1 = int32 edge index, 2 = int64

__device__ __forceinline__ uint32_t f2tf32(float f) {
    uint32_t r;
    asm("cvt.rna.tf32.f32 %0, %1;" : "=r"(r) : "f"(f));
    return r;
}

// -------- init + dtype probe --------
__global__ void k_init(const int* __restrict__ p, int n) {
    int i = blockIdx.x * blockDim.x + threadIdx.x;
    if (i < n) { g_cnt[i] = 0; g_cursor[i] = 0; }
    if (blockIdx.x == 0 && threadIdx.x == 0) {
        int nz = 0;
#pragma unroll
        for (int k = 0; k < 64; k++) nz |= p[2 * k + 1];
        g_elw = (nz == 0) ? 2 : 1;
    }
}

// -------- degree count: 4 edges/thread --------
__global__ void k_count(const int* __restrict__ p, int e, int n) {
    int base = (blockIdx.x * blockDim.x + threadIdx.x) * 4;
    if (base >= e) return;
    int elw = g_elw;
    int d[4];
    bool full = (base + 3 < e) && ((e & 3) == 0);
    if (elw == 1) {
        if (full) {
            int4 v = *(const int4*)(p + e + base);
            d[0] = v.x; d[1] = v.y; d[2] = v.z; d[3] = v.w;
        } else {
            for (int i = 0; i < 4; i++) d[i] = (base + i < e) ? p[e + base + i] : -1;
        }
    } else {
        const long long* q = (const long long*)p;
        if (full) {
            longlong2 v0 = *(const longlong2*)(q + e + base);
            longlong2 v1 = *(const longlong2*)(q + e + base + 2);
            d[0] = (int)v0.x; d[1] = (int)v0.y; d[2] = (int)v1.x; d[3] = (int)v1.y;
        } else {
            for (int i = 0; i < 4; i++) d[i] = (base + i < e) ? (int)q[e + base + i] : -1;
        }
    }
#pragma unroll
    for (int i = 0; i < 4; i++)
        if ((unsigned)d[i] < (unsigned)n) atomicAdd(&g_cnt[d[i]], 1);
}

// -------- scan A: per-1024 block scan + dinv --------
__global__ void k_scanA(int n) {
    __shared__ int sh[1024];
    int i = blockIdx.x * 1024 + threadIdx.x;
    int v = (i < n) ? g_cnt[i] : 0;
    if (i < n) g_dinv[i] = rsqrtf((float)(v + 1));
    sh[threadIdx.x] = v;
    __syncthreads();
#pragma unroll
    for (int off = 1; off < 1024; off <<= 1) {
        int t = (threadIdx.x >= off) ? sh[threadIdx.x - off] : 0;
        __syncthreads();
        sh[threadIdx.x] += t;
        __syncthreads();
    }
    if (i < n) g_rowtmp[i] = sh[threadIdx.x] - v;
    if (threadIdx.x == 1023) g_part[blockIdx.x] = sh[1023];
}

// -------- scan C: local scan of partials (scanB fused) --------
__global__ void k_scanC(int n, int e, int nb) {
    __shared__ int sh[128];
    int t = threadIdx.x & 127;
    // local exclusive scan of up to 128 block partials
    int v = (t < nb) ? g_part[t] : 0;
    sh[t] = v;
    __syncthreads();
#pragma unroll
    for (int off = 1; off < 128; off <<= 1) {
        int u = (t >= off) ? sh[t - off] : 0;
        __syncthreads();
        sh[t] += u;
        __syncthreads();
    }
    __shared__ int ex[128];
    ex[t] = sh[t] - v;
    __syncthreads();

    int i = blockIdx.x * blockDim.x + threadIdx.x;
    if (i < n) g_rowptr[i] = g_rowtmp[i] + ex[i >> 10];
    if (i == 0) g_rowptr[n] = e;
}

// -------- CSR fill: 4 edges/thread, packed int2 payload --------
__global__ void k_fill(const int* __restrict__ p, int e, int n) {
    int base = (blockIdx.x * blockDim.x + threadIdx.x) * 4;
    if (base >= e) return;
    int elw = g_elw;
    int s[4], d[4];
    bool full = (base + 3 < e) && ((e & 3) == 0);
    if (elw == 1) {
        if (full) {
            int4 vs = *(const int4*)(p + base);
            int4 vd = *(const int4*)(p + e + base);
            s[0] = vs.x; s[1] = vs.y; s[2] = vs.z; s[3] = vs.w;
            d[0] = vd.x; d[1] = vd.y; d[2] = vd.z; d[3] = vd.w;
        } else {
            for (int i = 0; i < 4; i++) {
                s[i] = (base + i < e) ? p[base + i] : -1;
                d[i] = (base + i < e) ? p[e + base + i] : -1;
            }
        }
    } else {
        const long long* q = (const long long*)p;
        if (full) {
            longlong2 s0 = *(const longlong2*)(q + base);
            longlong2 s1 = *(const longlong2*)(q + base + 2);
            longlong2 d0 = *(const longlong2*)(q + e + base);
            longlong2 d1 = *(const longlong2*)(q + e + base + 2);
            s[0] = (int)s0.x; s[1] = (int)s0.y; s[2] = (int)s1.x; s[3] = (int)s1.y;
            d[0] = (int)d0.x; d[1] = (int)d0.y; d[2] = (int)d1.x; d[3] = (int)d1.y;
        } else {
            for (int i = 0; i < 4; i++) {
                s[i] = (base + i < e) ? (int)q[base + i] : -1;
                d[i] = (base + i < e) ? (int)q[e + base + i] : -1;
            }
        }
    }
#pragma unroll
    for (int i = 0; i < 4; i++) {
        if ((unsigned)s[i] < (unsigned)n && (unsigned)d[i] < (unsigned)n) {
            int pos = g_rowptr[d[i]] + atomicAdd(&g_cursor[d[i]], 1);
            float nrm = g_dinv[s[i]] * g_dinv[d[i]];
            g_edge[pos] = make_int2(s[i], __float_as_int(nrm));
        }
    }
}

// -------- GEMM: g_H[n,64] = A[n,64] @ W[64,64] via tf32 mma.sync --------
template <int SRC>
__global__ void __launch_bounds__(128) k_gemm(const float* __restrict__ Aext,
                                              const float* __restrict__ W, int n) {
    __shared__ float As[64][68];
    __shared__ float Ws[64][72];

    const float* A = (SRC == 0) ? Aext : (const float*)g_A;
    int tid = threadIdx.x;
    int rowbase = blockIdx.x * 64;

#pragma unroll
    for (int i = 0; i < 8; i++) {
        int idx = tid + i * 128;
        int r = idx >> 4;
        int f4 = idx & 15;
        float4 va = (rowbase + r < n)
            ? *(const float4*)(A + (size_t)(rowbase + r) * 64 + f4 * 4)
            : make_float4(0.f, 0.f, 0.f, 0.f);
        As[r][f4 * 4 + 0] = __uint_as_float(f2tf32(va.x));
        As[r][f4 * 4 + 1] = __uint_as_float(f2tf32(va.y));
        As[r][f4 * 4 + 2] = __uint_as_float(f2tf32(va.z));
        As[r][f4 * 4 + 3] = __uint_as_float(f2tf32(va.w));
        float4 vw = *(const float4*)(W + r * 64 + f4 * 4);
        Ws[r][f4 * 4 + 0] = __uint_as_float(f2tf32(vw.x));
        Ws[r][f4 * 4 + 1] = __uint_as_float(f2tf32(vw.y));
        Ws[r][f4 * 4 + 2] = __uint_as_float(f2tf32(vw.z));
        Ws[r][f4 * 4 + 3] = __uint_as_float(f2tf32(vw.w));
    }
    __syncthreads();

    int warp = tid >> 5, lane = tid & 31;
    int gid = lane >> 2;
    int tig = lane & 3;
    int ar0 = warp * 16 + gid;
    int ar1 = ar0 + 8;

    float acc[8][4];
#pragma unroll
    for (int t = 0; t < 8; t++)
#pragma unroll
        for (int c = 0; c < 4; c++) acc[t][c] = 0.f;

#pragma unroll
    for (int ks = 0; ks < 8; ks++) {
        int k0 = ks * 8;
        uint32_t a0 = __float_as_uint(As[ar0][k0 + tig]);
        uint32_t a1 = __float_as_uint(As[ar1][k0 + tig]);
        uint32_t a2 = __float_as_uint(As[ar0][k0 + tig + 4]);
        uint32_t a3 = __float_as_uint(As[ar1][k0 + tig + 4]);
#pragma unroll
        for (int nt = 0; nt < 8; nt++) {
            uint32_t b0 = __float_as_uint(Ws[k0 + tig][nt * 8 + gid]);
            uint32_t b1 = __float_as_uint(Ws[k0 + tig + 4][nt * 8 + gid]);
            asm volatile(
                "mma.sync.aligned.m16n8k8.row.col.f32.tf32.tf32.f32 "
                "{%0,%1,%2,%3}, {%4,%5,%6,%7}, {%8,%9}, {%0,%1,%2,%3};"
                : "+f"(acc[nt][0]), "+f"(acc[nt][1]), "+f"(acc[nt][2]), "+f"(acc[nt][3])
                : "r"(a0), "r"(a1), "r"(a2), "r"(a3), "r"(b0), "r"(b1));
        }
    }

    int row0 = rowbase + warp * 16 + gid;
    int row1 = row0 + 8;
#pragma unroll
    for (int nt = 0; nt < 8; nt++) {
        int col = nt * 8 + tig * 2;
        if (row0 < n)
            *(float2*)(g_H + (size_t)row0 * 64 + col) = make_float2(acc[nt][0], acc[nt][1]);
        if (row1 < n)
            *(float2*)(g_H + (size_t)row1 * 64 + col) = make_float2(acc[nt][2], acc[nt][3]);
    }
}

// -------- Aggregation (warp per node, float2, int2 edge payload) --------
template <int DSTOUT>
__global__ void k_agg(const float* __restrict__ bias, float* __restrict__ outext,
                      int n) {
    int gw = (blockIdx.x * blockDim.x + threadIdx.x) >> 5;
    int lane = threadIdx.x & 31;
    if (gw >= n) return;
    int i = gw;

    const float2* H2 = (const float2*)g_H;
    float di = g_dinv[i];
    float sn = di * di;
    float2 h = H2[i * 32 + lane];
    float2 acc = make_float2(h.x * sn, h.y * sn);

    int s = g_rowptr[i], e = g_rowptr[i + 1];
    for (int base = s; base < e; base += 32) {
        int m = min(32, e - base);
        int c = 0; float nv = 0.f;
        if (lane < m) {
            int2 ed = g_edge[base + lane];
            c = ed.x; nv = __int_as_float(ed.y);
        }
#pragma unroll 4
        for (int j = 0; j < m; j++) {
            int   cj = __shfl_sync(0xffffffffu, c, j);
            float nj = __shfl_sync(0xffffffffu, nv, j);
            float2 hh = __ldg(&H2[cj * 32 + lane]);
            acc.x += hh.x * nj;
            acc.y += hh.y * nj;
        }
    }
    float2 bb = ((const float2*)bias)[lane];
    acc.x = fmaxf(acc.x + bb.x, 0.f);
    acc.y = fmaxf(acc.y + bb.y, 0.f);
    float2* outp = (DSTOUT == 0) ? (float2*)g_A : (float2*)outext;
    outp[i * 32 + lane] = acc;
}

// -------- launch --------
extern "C" void kernel_launch(void* const* d_in, const int* in_sizes, int n_in,
                              void* d_out, int out_size) {
    const float* x  = (const float*)d_in[0];
    const int*   ei = (const int*)d_in[1];
    const float* W0 = (const float*)d_in[2];
    const float* b0 = (const float*)d_in[3];
    const float* W1 = (const float*)d_in[4];
    const float* b1 = (const float*)d_in[5];
    const float* W2 = (const float*)d_in[6];
    const float* b2 = (const float*)d_in[7];
    float* out = (float*)d_out;

    int n = in_sizes[0] / D;
    int e = in_sizes[1] / 2;
    int nb = (n + 1023) / 1024;
    int e4 = (e + 3) / 4;

    k_init <<<(n + 255) / 256, 256>>>(ei, n);
    k_count<<<(e4 + 255) / 256, 256>>>(ei, e, n);
    k_scanA<<<nb, 1024>>>(n);
    k_scanC<<<(n + 255) / 256, 256>>>(n, e, nb);
    k_fill <<<(e4 + 255) / 256, 256>>>(ei, e, n);

    int gemm_blocks = (n + 63) / 64;
    int agg_blocks  = (n + 7) / 8;

    k_gemm<0><<<gemm_blocks, 128>>>(x, W0, n);
    k_agg<0> <<<agg_blocks, 256>>>(b0, nullptr, n);
    k_gemm<1><<<gemm_blocks, 128>>>(nullptr, W1, n);
    k_agg<0> <<<agg_blocks, 256>>>(b1, nullptr, n);
    k_gemm<1><<<gemm_blocks, 128>>>(nullptr, W2, n);
    k_agg<1> <<<agg_blocks, 256>>>(b2, out, n);
}